// round 8
// baseline (speedup 1.0000x reference)
#include <cuda_runtime.h>
#include <math.h>

#define DD 256
#define HH 512
#define BB 128
typedef unsigned long long ull;

__device__ __forceinline__ ull packf2(float lo, float hi) {
    return ((ull)__float_as_uint(hi) << 32) | (ull)__float_as_uint(lo);
}
__device__ __forceinline__ float lof(ull v) { return __uint_as_float((unsigned)v); }
__device__ __forceinline__ float hif(ull v) { return __uint_as_float((unsigned)(v >> 32)); }
__device__ __forceinline__ void ffma2(ull& d, ull a, ull b) {
    asm("fma.rn.f32x2 %0, %1, %2, %0;" : "+l"(d) : "l"(a), "l"(b));
}

// Wide weights, fp32 pairs, split into independently-predicated streams.
__device__ ulonglong2 g_wA[260 * 512];  // (w0.mu,w0.lv), (w1s0.mu,w1s0.lv)
__device__ ull g_wA2[260 * 512];        // (w1s1.mu, w1s1.lv)
__device__ ull g_wO[260 * 512];         // (wo0, wo1)
// Warm-up 3rd-slot: idx<512 -> i=2, idx>=512 -> i=3
__device__ ull g_w3p[2 * 512];
__device__ float g_w3o[2 * 512];
// Combiner urgent records (fp32)
__device__ float g_recS[256 * 40];   // steady 2-slot layout (i>=4)
__device__ float g_recW[4 * 68];     // warm-up 3-slot layout (i<4)

__device__ __forceinline__ int permf(int p) {
    if (p < 3) return (p == 0) ? 0 : ((p == 1) ? 255 : 510);
    if (p < 6) { int q = p - 3; return (q == 0) ? 1 : ((q == 1) ? 256 : 511); }
    int d = 3 + ((p - 6) >> 1);
    return (((p - 6) & 1) == 0) ? (d - 1) : (d + 254);
}
__device__ __forceinline__ int degf(int p) {
    if (p < 3) return 1;
    if (p < 6) return 2;
    return 3 + ((p - 6) >> 1);
}
__device__ __forceinline__ int Pof(int k) {
    if (k <= 0) return 0;
    if (k == 1) return 3;
    int v = 2 * k + 2;
    return v > HH ? HH : v;
}
__device__ __forceinline__ float elu1(float a) {
    float e = __expf(a) - 1.f;
    return a > 0.f ? a : e;
}

__global__ void setup_kernel(
    const float* __restrict__ W0m, const float* __restrict__ W1m, const float* __restrict__ Wom,
    const float* __restrict__ b0m, const float* __restrict__ b1m,
    const float* __restrict__ W0l, const float* __restrict__ W1l, const float* __restrict__ Wol,
    const float* __restrict__ b0l, const float* __restrict__ b1l,
    const float* __restrict__ bom, const float* __restrict__ bol)
{
    int tid = blockIdx.x * blockDim.x + threadIdx.x;
    int stride = gridDim.x * blockDim.x;

    for (int idx = tid; idx < 256 * 512; idx += stride) {
        int i = idx >> 9, u = idx & 511;
        int du = degf(u), ou = permf(u);
        int onet = u >> 8, ocol = u & 255;
        const float* Wo = onet ? Wol : Wom;

        int w0row = i - 1 < 0 ? 0 : i - 1;
        float m0 = (du >= w0row + 1) ? 1.f : 0.f;
        float w0mu = m0 * W0m[ou * DD + w0row];
        float w0lv = m0 * W0l[ou * DD + w0row];

        int pB = Pof(i - 2);
        float w1s[2][2], wos[2];
#pragma unroll
        for (int s = 0; s < 2; s++) {
            int p = pB + s; if (p > HH - 1) p = HH - 1;
            int op = permf(p), dp = degf(p);
            float m1 = (du >= dp) ? 1.f : 0.f;
            w1s[s][0] = m1 * W1m[ou * HH + op];
            w1s[s][1] = m1 * W1l[ou * HH + op];
            float mo = (ocol >= dp) ? 1.f : 0.f;
            wos[s] = mo * Wo[ocol * HH + op];
        }
        g_wA[i * 512 + u] = make_ulonglong2(packf2(w0mu, w0lv), packf2(w1s[0][0], w1s[0][1]));
        g_wA2[i * 512 + u] = packf2(w1s[1][0], w1s[1][1]);
        g_wO[i * 512 + u] = packf2(wos[0], wos[1]);
    }
    for (int idx = tid; idx < 1024; idx += stride) {
        int j = idx >> 9, u = idx & 511;
        int du = degf(u), ou = permf(u);
        int onet = u >> 8, ocol = u & 255;
        const float* Wo = onet ? Wol : Wom;
        int p = (j == 0) ? 2 : 5;
        int op = permf(p), dp = degf(p);
        float m1 = (du >= dp) ? 1.f : 0.f;
        float mo = (ocol >= dp) ? 1.f : 0.f;
        g_w3p[idx] = packf2(m1 * W1m[ou * HH + op], m1 * W1l[ou * HH + op]);
        g_w3o[idx] = mo * Wo[ocol * HH + op];
    }
    for (int i = tid; i < 256; i += stride) {
        int cB = Pof(i - 1), cc = Pof(i) - cB;
        int pB = Pof(i - 2), cp = Pof(i - 1) - pB;
        {
            float* r = g_recS + i * 40;
            for (int k = 0; k < 40; k++) r[k] = 0.f;
            int c2 = cc < 2 ? cc : 2, p2 = cp < 2 ? cp : 2;
            for (int s = 0; s < c2; s++) {
                int p = permf(cB + s);
                if (i >= 1) { r[0 + 2 * s] = W0m[p * DD + (i - 1)]; r[1 + 2 * s] = W0l[p * DD + (i - 1)]; }
                r[4 + 2 * s] = b0m[p];  r[5 + 2 * s] = b0l[p];
                r[8 + 2 * s] = b1m[p];  r[9 + 2 * s] = b1l[p];
                r[32 + 2 * s] = Wom[i * HH + p]; r[33 + 2 * s] = Wol[i * HH + p];
            }
            for (int sp = 0; sp < p2; sp++) {
                int pp = permf(pB + sp);
                r[28 + 2 * sp] = Wom[i * HH + pp]; r[29 + 2 * sp] = Wol[i * HH + pp];
                for (int sc = 0; sc < c2; sc++) {
                    int g = permf(cB + sc);
                    r[12 + sp * 4 + 2 * sc] = W1m[g * HH + pp];
                    r[13 + sp * 4 + 2 * sc] = W1l[g * HH + pp];
                }
            }
            for (int sp = 0; sp < c2; sp++)
                for (int sc = 0; sc < c2; sc++) {
                    int pp = permf(cB + sp), g = permf(cB + sc);
                    r[20 + sp * 4 + 2 * sc] = W1m[g * HH + pp];
                    r[21 + sp * 4 + 2 * sc] = W1l[g * HH + pp];
                }
            r[36] = bom[i]; r[37] = bol[i];
        }
        if (i < 4) {
            float* r = g_recW + i * 68;
            for (int k = 0; k < 68; k++) r[k] = 0.f;
            for (int s = 0; s < cc; s++) {
                int p = permf(cB + s);
                if (i >= 1) { r[0 + 2 * s] = W0m[p * DD + (i - 1)]; r[1 + 2 * s] = W0l[p * DD + (i - 1)]; }
                r[6 + 2 * s] = b0m[p];  r[7 + 2 * s] = b0l[p];
                r[12 + 2 * s] = b1m[p]; r[13 + 2 * s] = b1l[p];
                r[60 + 2 * s] = Wom[i * HH + p]; r[61 + 2 * s] = Wol[i * HH + p];
            }
            for (int sp = 0; sp < cp; sp++) {
                int pp = permf(pB + sp);
                r[54 + 2 * sp] = Wom[i * HH + pp]; r[55 + 2 * sp] = Wol[i * HH + pp];
                for (int sc = 0; sc < cc; sc++) {
                    int g = permf(cB + sc);
                    r[18 + sp * 6 + 2 * sc] = W1m[g * HH + pp];
                    r[19 + sp * 6 + 2 * sc] = W1l[g * HH + pp];
                }
            }
            for (int sp = 0; sp < cc; sp++)
                for (int sc = 0; sc < cc; sc++) {
                    int pp = permf(cB + sp), g = permf(cB + sc);
                    r[36 + sp * 6 + 2 * sc] = W1m[g * HH + pp];
                    r[37 + sp * 6 + 2 * sc] = W1l[g * HH + pp];
                }
            r[66] = bom[i]; r[67] = bol[i];
        }
    }
}

// smem layout (floats)
#define OFF_RECS 0
#define OFF_RECW 10240
#define OFF_XS   10512
#define OFF_PUB  10768
#define OFF_PAR  10800
#define SM_FLOATS 10832

struct CombState {
    float h0p[3][2], h1p[3][2];
    float ncol, lvsum;
};

// single-thread warm path (i<4), proven; run redundantly on 4 lanes
__device__ __forceinline__ void comb_warm(const float* __restrict__ pr, const float* __restrict__ r,
                                          float xi, CombState& st, float* __restrict__ pu,
                                          float* __restrict__ outp)
{
    float h0c[3][2], h1c[3][2];
#pragma unroll
    for (int s = 0; s < 3; s++)
#pragma unroll
        for (int n = 0; n < 2; n++) {
            float pa0 = (s < 2) ? pr[4 * s + n] : pr[8 + n];
            h0c[s][n] = elu1(pa0 + st.ncol * r[2 * s + n] + r[6 + 2 * s + n]);
        }
#pragma unroll
    for (int sc = 0; sc < 3; sc++)
#pragma unroll
        for (int n = 0; n < 2; n++) {
            float a = ((sc < 2) ? pr[4 * sc + 2 + n] : pr[10 + n]) + r[12 + 2 * sc + n];
#pragma unroll
            for (int sp = 0; sp < 3; sp++) a = fmaf(st.h0p[sp][n], r[18 + sp * 6 + 2 * sc + n], a);
#pragma unroll
            for (int sp = 0; sp < 3; sp++) a = fmaf(h0c[sp][n], r[36 + sp * 6 + 2 * sc + n], a);
            h1c[sc][n] = elu1(a);
        }
    float mu = pr[12] + r[66];
    float lv = pr[13] + r[67];
#pragma unroll
    for (int sp = 0; sp < 3; sp++) { mu = fmaf(st.h1p[sp][0], r[54 + 2 * sp], mu); lv = fmaf(st.h1p[sp][1], r[55 + 2 * sp], lv); }
#pragma unroll
    for (int sc = 0; sc < 3; sc++) { mu = fmaf(h1c[sc][0], r[60 + 2 * sc], mu); lv = fmaf(h1c[sc][1], r[61 + 2 * sc], lv); }
    float ls = 0.5f * lv;
    float nc = (xi - mu) * __expf(-ls);
    st.lvsum += ls; st.ncol = nc;
    *outp = nc;
    *(ull*)(pu + 0) = packf2(nc, nc);
    *(ull*)(pu + 2) = packf2(h0c[0][0], h0c[0][1]);
    *(ull*)(pu + 4) = packf2(h0c[1][0], h0c[1][1]);
    *(ull*)(pu + 6) = packf2(h1c[0][0], h1c[1][0]);
    *(ull*)(pu + 8) = packf2(h1c[0][1], h1c[1][1]);
    *(ull*)(pu + 10) = packf2(h0c[2][0], h0c[2][1]);
    *(ull*)(pu + 12) = packf2(h1c[2][0], h1c[2][1]);
#pragma unroll
    for (int s = 0; s < 3; s++)
#pragma unroll
        for (int n = 0; n < 2; n++) { st.h0p[s][n] = h0c[s][n]; st.h1p[s][n] = h1c[s][n]; }
}

// 4-lane steady combiner: lane = n*2 + s (n = net, s = slot)
__device__ __forceinline__ void comb_steady4(
    int lane, const float* __restrict__ pr, const float* __restrict__ r, float xi,
    float& st_ncol, float* __restrict__ h0own, float* __restrict__ h1own,
    float& lvs, float* __restrict__ pu, float* __restrict__ outp)
{
    const int n = lane >> 1, s = lane & 1;
    float h0 = elu1(pr[4 * s + n] + st_ncol * r[2 * s + n] + r[4 + 2 * s + n]);
    float h0o = __shfl_xor_sync(0xFu, h0, 1);
    const float h0s0 = (s == 0) ? h0 : h0o;
    const float h0s1 = (s == 0) ? h0o : h0;

    float a = pr[4 * s + 2 + n] + r[8 + 2 * s + n];
    a = fmaf(h0own[0], r[12 + 2 * s + n], a);
    a = fmaf(h0own[1], r[16 + 2 * s + n], a);
    a = fmaf(h0s0, r[20 + 2 * s + n], a);
    a = fmaf(h0s1, r[24 + 2 * s + n], a);
    float h1 = elu1(a);
    float h1o = __shfl_xor_sync(0xFu, h1, 1);
    const float h1s0 = (s == 0) ? h1 : h1o;
    const float h1s1 = (s == 0) ? h1o : h1;

    // m = mu for n==0 lanes, lv for n==1 lanes
    float m = pr[12 + n] + r[36 + n];
    m = fmaf(h1own[0], r[28 + n], m);
    m = fmaf(h1own[1], r[30 + n], m);
    m = fmaf(h1s0, r[32 + n], m);
    m = fmaf(h1s1, r[34 + n], m);
    const float ls = 0.5f * m;
    const float e = __expf(-ls);
    const float e2 = __shfl_sync(0xFu, e, 2);        // lane2's exp(-logstd)
    const float nc = (xi - m) * e2;                  // valid at lane 0
    if (lane == 2) lvs += ls;

    if (lane == 0) {
        *(ull*)(pu + 0) = packf2(nc, nc);
        pu[2] = h0; pu[6] = h1;
        *outp = nc;
    } else if (lane == 1) { pu[4] = h0; pu[7] = h1; }
    else if (lane == 2)   { pu[3] = h0; pu[8] = h1; }
    else                  { pu[5] = h0; pu[9] = h1; }

    h0own[0] = h0s0; h0own[1] = h0s1;
    h1own[0] = h1s0; h1own[1] = h1s1;
    st_ncol = __shfl_sync(0xFu, nc, 0);
}

__device__ __forceinline__ void wide_step(
    int i, const float* __restrict__ pb, const float* __restrict__ pbh,
    const float* __restrict__ pb12,
    ulonglong2 Wa, ull Wa2, ull Wo,
    ull& A0, ull& A1, ull& AO, float& aoutC,
    int pubA, int pubO, float* __restrict__ pwA, float* __restrict__ pwO,
    ull w3p2, ull w3p3, float w3o2, float w3o3)
{
    if (i <= pubA) {
        const ull nc2  = *(const ull*)(pb + 0);
        const ull h0s0 = *(const ull*)(pb + 2);
        const ull h0s1 = *(const ull*)(pb + 4);
        ffma2(A0, nc2, Wa.x);
        ffma2(A1, h0s0, Wa.y);
        ffma2(A1, h0s1, Wa2);
        if ((unsigned)(i - 2) < 2u) {
            const ull h0s2 = *(const ull*)(pb + 10);
            ffma2(A1, h0s2, (i == 2) ? w3p2 : w3p3);
        }
        if (i == pubA) { *(ull*)(pwA + 0) = A0; *(ull*)(pwA + 2) = A1; }
    }
    if (i <= pubO) {
        const ull h1p = *(const ull*)pbh;
        ffma2(AO, h1p, Wo);
        if ((unsigned)(i - 2) < 2u) aoutC = fmaf(*pb12, (i == 2) ? w3o2 : w3o3, aoutC);
        if (i == pubO) *pwO = lof(AO) + hif(AO) + aoutC;
    }
}

// 128 CTAs (one batch element each), 544 threads:
// tid<512: wide owner of unit tid + output column (tid>>8, tid&255)
// tid 512..515: 4-lane combiner
__global__ __launch_bounds__(544, 1) void made_kernel(
    const float* __restrict__ x, float* __restrict__ out)
{
    __shared__ __align__(16) float SM[SM_FLOATS];

    const int tid = threadIdx.x;
    const int b = blockIdx.x;

    {
        const float4* src = (const float4*)g_recS;
        float4* dst = (float4*)(SM + OFF_RECS);
        for (int k = tid; k < (256 * 40) / 4; k += 544) dst[k] = src[k];
        for (int k = tid; k < 4 * 68; k += 544) SM[OFF_RECW + k] = g_recW[k];
        if (tid < 256) SM[OFF_XS + tid] = x[b * DD + tid];
        for (int k = tid; k < 64; k += 544) SM[OFF_PUB + k] = 0.f;
    }

    const int u = tid < 512 ? tid : 0;
    const int du = degf(u);
    const int su = u - Pof(du - 1);
    const int onet = (tid >> 8) & 1;
    const int ocol = tid & 255;
    const int pubA = du - 1;
    const int pubO = ocol - 1;
    const int off = (su < 2) ? (su << 2) : 8;

    float* const pub0 = SM + OFF_PUB;
    float* const pub1 = SM + OFF_PUB + 16;
    float* const par0 = SM + OFF_PAR;
    float* const par1 = SM + OFF_PAR + 16;
    float* const pwA0 = par0 + off;
    float* const pwA1 = par1 + off;
    float* const pwO0 = par0 + 12 + onet;
    float* const pwO1 = par1 + 12 + onet;
    const float* const pbh0 = pub0 + 6 + 2 * onet;
    const float* const pbh1 = pub1 + 6 + 2 * onet;
    const float* const pb120 = pub0 + 12 + onet;
    const float* const pb121 = pub1 + 12 + onet;

    ull A0 = 0, A1 = 0, AO = 0;
    float aoutC = 0.f;

    const ulonglong2* wA = g_wA + u;
    const ull* wA2 = g_wA2 + u;
    const ull* wO = g_wO + u;
    ulonglong2 Wa0 = wA[0];   ull Wa20 = wA2[0];   ull Wo0 = wO[0];
    ulonglong2 Wa1 = wA[512]; ull Wa21 = wA2[512]; ull Wo1 = wO[512];
    const ull w3p2 = g_w3p[u], w3p3 = g_w3p[512 + u];
    const float w3o2 = g_w3o[u], w3o3 = g_w3o[512 + u];

    // combiner state
    const int lane = tid & 3;
    const int cn = lane >> 1;
    CombState st;
#pragma unroll
    for (int s = 0; s < 3; s++)
#pragma unroll
        for (int n2 = 0; n2 < 2; n2++) { st.h0p[s][n2] = 0.f; st.h1p[s][n2] = 0.f; }
    st.ncol = 0.f; st.lvsum = 0.f;
    float st_ncol = 0.f, lvs = 0.f;
    float h0own[2] = {0.f, 0.f}, h1own[2] = {0.f, 0.f};

    float* const outb = out + b * DD;

    __syncthreads();

#pragma unroll 1
    for (int i = 0; i < DD; i += 2) {
        // even sub-step: wide reads pub1/writes par1; combiner reads par0/writes pub0
        if (tid < 512) {
            wide_step(i, pub1, pbh1, pb121, Wa0, Wa20, Wo0, A0, A1, AO, aoutC,
                      pubA, pubO, pwA1, pwO1, w3p2, w3p3, w3o2, w3o3);
            if (i + 2 <= pubA) { Wa0 = wA[(i + 2) << 9]; Wa20 = wA2[(i + 2) << 9]; }
            if (i + 2 <= pubO) { Wo0 = wO[(i + 2) << 9]; }
        } else if (tid < 516) {
            const float xi = SM[OFF_XS + i];
            if (i >= 4) {
                comb_steady4(lane, par0, SM + OFF_RECS + i * 40, xi,
                             st_ncol, h0own, h1own, lvs, pub0, outb + i);
            } else {
                comb_warm(par0, SM + OFF_RECW + i * 68, xi, st, pub0, outb + i);
                st_ncol = st.ncol; lvs = st.lvsum;
                h0own[0] = st.h0p[0][cn]; h0own[1] = st.h0p[1][cn];
                h1own[0] = st.h1p[0][cn]; h1own[1] = st.h1p[1][cn];
            }
        }
        __syncthreads();
        // odd sub-step: wide reads pub0/writes par0; combiner reads par1/writes pub1
        if (tid < 512) {
            wide_step(i + 1, pub0, pbh0, pb120, Wa1, Wa21, Wo1, A0, A1, AO, aoutC,
                      pubA, pubO, pwA0, pwO0, w3p2, w3p3, w3o2, w3o3);
            if (i + 3 <= pubA) { Wa1 = wA[(i + 3) << 9]; Wa21 = wA2[(i + 3) << 9]; }
            if (i + 3 <= pubO) { Wo1 = wO[(i + 3) << 9]; }
        } else if (tid < 516) {
            const float xi = SM[OFF_XS + i + 1];
            if (i + 1 >= 4) {
                comb_steady4(lane, par1, SM + OFF_RECS + (i + 1) * 40, xi,
                             st_ncol, h0own, h1own, lvs, pub1, outb + i + 1);
            } else {
                comb_warm(par1, SM + OFF_RECW + (i + 1) * 68, xi, st, pub1, outb + i + 1);
                st_ncol = st.ncol; lvs = st.lvsum;
                h0own[0] = st.h0p[0][cn]; h0own[1] = st.h0p[1][cn];
                h1own[0] = st.h1p[0][cn]; h1own[1] = st.h1p[1][cn];
            }
        }
        __syncthreads();
    }

    if (tid == 514) out[BB * DD + b] = lvs;
}

extern "C" void kernel_launch(void* const* d_in, const int* in_sizes, int n_in,
                              void* d_out, int out_size) {
    const float* xx   = (const float*)d_in[0];
    const float* muW0 = (const float*)d_in[1];
    const float* mub0 = (const float*)d_in[2];
    const float* muW1 = (const float*)d_in[3];
    const float* mub1 = (const float*)d_in[4];
    const float* muWo = (const float*)d_in[5];
    const float* mubo = (const float*)d_in[6];
    const float* lvW0 = (const float*)d_in[7];
    const float* lvb0 = (const float*)d_in[8];
    const float* lvW1 = (const float*)d_in[9];
    const float* lvb1 = (const float*)d_in[10];
    const float* lvWo = (const float*)d_in[11];
    const float* lvbo = (const float*)d_in[12];
    float* out = (float*)d_out;

    setup_kernel<<<512, 256>>>(muW0, muW1, muWo, mub0, mub1,
                               lvW0, lvW1, lvWo, lvb0, lvb1, mubo, lvbo);
    made_kernel<<<BB, 544>>>(xx, out);
}